// round 17
// baseline (speedup 1.0000x reference)
#include <cuda_runtime.h>
#include <cuda_bf16.h>
#include <cuda_fp16.h>
#include <cstdint>
#include <cstddef>

#define NN 50000
#define EE 800000

// ---------------- scratch layout (floats) ----------------
constexpr size_t OFF_P     = 0;                              // N*384: [xl fp32 | (unused) | B fp32]; later z1 bf16
constexpr size_t OFF_HMOD  = OFF_P     + (size_t)NN * 384;   // bf16 hi/lo staging
constexpr size_t OFF_LOGIT = OFF_HMOD  + (size_t)NN * 128;   // XLH: x_l fp16 rows (N*128 half = 3.2M floats)
constexpr size_t OFF_AMAX  = OFF_LOGIT + (size_t)EE * 4;
constexpr size_t OFF_DENOM = OFF_AMAX  + (size_t)NN * 4;
constexpr size_t OFF_AGGR  = OFF_DENOM + (size_t)NN * 4;     // CSR ints (~0.9M) then AH fp16 at +1M floats
constexpr size_t OFF_AGGR2 = OFF_AGGR  + (size_t)NN * 128;   // x_r temp, then Wp out fp32
constexpr size_t OFF_STYLE = OFF_AGGR2 + (size_t)NN * 128;   // 256
constexpr size_t OFF_BIAS2 = OFF_STYLE + 256;                // 128
constexpr size_t OFF_ZERO  = OFF_BIAS2 + 128;                // 128
constexpr size_t OFF_WSTG  = OFF_ZERO + 128;                 // 131072 uint32 staged weights
constexpr size_t SCRATCH_TOTAL = OFF_WSTG + 131072;

constexpr size_t OFF_AH = OFF_AGGR + 1000000;                // A fp16 rows (N*128 half)

constexpr int WS_WL = 0;
constexpr int WS_WR = 16384;
constexpr int WS_WE = 32768;
constexpr int WS_WP = 49152;
constexpr int WS_W1 = 65536;
constexpr int WS_W2 = 98304;

__device__ __align__(16) float g_scratch[SCRATCH_TOTAL];
__device__ int g_is64;

__device__ __forceinline__ int* csr_base() { return (int*)(g_scratch + OFF_AGGR); }

// ---------------- helpers ----------------
__device__ __forceinline__ float geluf(float x) {
    return 0.5f * x * (1.f + erff(x * 0.70710678118654752440f));
}
__device__ __forceinline__ int eidx(const int* __restrict__ ei32, size_t pos, int is64, int M) {
    int v = ei32[is64 ? (pos << 1) : pos];
    if ((unsigned)v >= (unsigned)M) v = 0;
    return v;
}
__device__ __forceinline__ uint32_t s2u(const void* p) {
    uint32_t a;
    asm("{ .reg .u64 t; cvta.to.shared.u64 t, %1; cvt.u32.u64 %0, t; }" : "=r"(a) : "l"(p));
    return a;
}
__device__ __forceinline__ void ldsm_x4(uint32_t& r0, uint32_t& r1, uint32_t& r2, uint32_t& r3, uint32_t addr) {
    asm volatile("ldmatrix.sync.aligned.m8n8.x4.shared.b16 {%0,%1,%2,%3}, [%4];"
                 : "=r"(r0), "=r"(r1), "=r"(r2), "=r"(r3) : "r"(addr));
}
__device__ __forceinline__ void ldsm_x2(uint32_t& r0, uint32_t& r1, uint32_t addr) {
    asm volatile("ldmatrix.sync.aligned.m8n8.x2.shared.b16 {%0,%1}, [%2];"
                 : "=r"(r0), "=r"(r1) : "r"(addr));
}
__device__ __forceinline__ void mma_bf16(float* c, uint32_t a0, uint32_t a1, uint32_t a2, uint32_t a3,
                                         uint32_t b0, uint32_t b1) {
    asm volatile("mma.sync.aligned.m16n8k16.row.col.f32.bf16.bf16.f32 "
                 "{%0,%1,%2,%3}, {%4,%5,%6,%7}, {%8,%9}, {%0,%1,%2,%3};"
                 : "+f"(c[0]), "+f"(c[1]), "+f"(c[2]), "+f"(c[3])
                 : "r"(a0), "r"(a1), "r"(a2), "r"(a3), "r"(b0), "r"(b1));
}
__device__ __forceinline__ uint32_t pack_split(float a, float b, uint32_t& lo) {
    __nv_bfloat16 ha = __float2bfloat16(a), hb = __float2bfloat16(b);
    float ra = a - __bfloat162float(ha), rb = b - __bfloat162float(hb);
    __nv_bfloat16 la = __float2bfloat16(ra), lb = __float2bfloat16(rb);
    unsigned short uha = *(unsigned short*)&ha, uhb = *(unsigned short*)&hb;
    unsigned short ula = *(unsigned short*)&la, ulb = *(unsigned short*)&lb;
    lo = (uint32_t)ula | ((uint32_t)ulb << 16);
    return (uint32_t)uha | ((uint32_t)uhb << 16);
}

// ---------------- merged setup ----------------
__device__ __forceinline__ void wconv_one(const float* __restrict__ W, int kdim, int ndim,
                                          int dstOff, int t) {
    int kh = kdim >> 1;
    int tot = ndim * kh;
    if (t >= tot) return;
    int n = t / kh, kp = t % kh;
    float a = W[(size_t)(2 * kp) * ndim + n];
    float b = W[(size_t)(2 * kp + 1) * ndim + n];
    uint32_t l, h = pack_split(a, b, l);
    uint32_t* ws = (uint32_t*)(g_scratch + OFF_WSTG) + dstOff;
    ws[(size_t)n * kh + kp] = h;
    ws[(size_t)tot + (size_t)n * kh + kp] = l;
}

__global__ void k_setup(const int* __restrict__ ei,
                        const float* __restrict__ t_emb, const float* __restrict__ fcW,
                        const float* __restrict__ fcb, const float* __restrict__ gatb,
                        const float* __restrict__ Wp, const float* __restrict__ bp,
                        const float* __restrict__ Wl, const float* __restrict__ Wr,
                        const float* __restrict__ We, const float* __restrict__ W1,
                        const float* __restrict__ W2, int E, int M) {
    int b = blockIdx.x, t = threadIdx.x;
    int ZB = (M + 255) >> 8;
    if (b == 0) {
        float s = fcb[t];
        for (int i = 0; i < 128; i++) s += t_emb[i] * fcW[i * 256 + t];
        g_scratch[OFF_STYLE + t] = s;
        return;
    }
    b -= 1;
    if (b == 0) {
        if (t < 128) {
            float s = bp[t];
            for (int i = 0; i < 128; i++) s += gatb[i] * Wp[i * 128 + t];
            g_scratch[OFF_BIAS2 + t] = s;
        } else if (t == 128) {
            int z = 0;
#pragma unroll
            for (int i = 0; i < 16; i++) z |= ei[2 * i + 1];
            g_is64 = (z == 0) ? 1 : 0;
        }
        return;
    }
    b -= 1;
    if (b < ZB) {
        int i = b * 256 + t;
        if (i < M) csr_base()[E + M + 1 + i] = 0;
        return;
    }
    b -= ZB;
    if (b < 32) { wconv_one(Wl, 128, 128, WS_WL, b * 256 + t); return; }
    b -= 32;
    if (b < 32) { wconv_one(Wr, 128, 128, WS_WR, b * 256 + t); return; }
    b -= 32;
    if (b < 32) { wconv_one(We, 128, 128, WS_WE, b * 256 + t); return; }
    b -= 32;
    if (b < 32) { wconv_one(Wp, 128, 128, WS_WP, b * 256 + t); return; }
    b -= 32;
    if (b < 64) { wconv_one(W1, 128, 256, WS_W1, b * 256 + t); return; }
    b -= 64;
    if (b < 64) { wconv_one(W2, 256, 128, WS_W2, b * 256 + t); return; }
}

// ---------------- CSR build ----------------
__global__ void k_prep(const int* __restrict__ ei, int E, int M) {
    int e = blockIdx.x * 256 + threadIdx.x;
    if (e >= E) return;
    int d = eidx(ei, (size_t)E + e, g_is64, M);
    atomicAdd(&csr_base()[E + M + 1 + d], 1);
}
__global__ void __launch_bounds__(1024) k_scan(int E, int M) {
    __shared__ int ssum[1024];
    int* IA = csr_base();
    int* off = IA + E;
    int* cur = IA + E + M + 1;
    int t = threadIdx.x;
    int C = (M + 1023) >> 10;
    int lo = t * C, hi = lo + C; if (hi > M) hi = M; if (lo > M) lo = M;
    int s = 0;
    for (int i = lo; i < hi; i++) s += cur[i];
    ssum[t] = s;
    __syncthreads();
    for (int o = 1; o < 1024; o <<= 1) {
        int v = (t >= o) ? ssum[t - o] : 0;
        __syncthreads();
        ssum[t] += v;
        __syncthreads();
    }
    int pre = (t == 0) ? 0 : ssum[t - 1];
    for (int i = lo; i < hi; i++) {
        int d = cur[i];
        off[i] = pre;
        cur[i] = pre;
        pre += d;
    }
    if (t == 1023) off[M] = ssum[1023];
}
__global__ void k_fill(const int* __restrict__ ei, int E, int M) {
    int e = blockIdx.x * 256 + threadIdx.x;
    if (e >= E) return;
    int is64 = g_is64;
    int s = eidx(ei, (size_t)e, is64, M);
    int d = eidx(ei, (size_t)E + e, is64, M);
    int* IA = csr_base();
    int p = atomicAdd(&IA[E + M + 1 + d], 1);
    IA[p] = s;
}

// ---------------- AdaGN (warp per node, float4) -> packed bf16 hi/lo ----------------
__global__ void __launch_bounds__(256) k_adagn(const float* __restrict__ hs,
                                               const float* __restrict__ gnw,
                                               const float* __restrict__ gnb, int M) {
    int n = blockIdx.x * 8 + (threadIdx.x >> 5);
    if (n >= M) return;
    int l = threadIdx.x & 31;
    float4 v = ((const float4*)(hs + (size_t)n * 128))[l];
    float s = v.x + v.y + v.z + v.w;
    float q = v.x * v.x + v.y * v.y + v.z * v.z + v.w * v.w;
    s += __shfl_xor_sync(0xffffffffu, s, 1);
    q += __shfl_xor_sync(0xffffffffu, q, 1);
    s += __shfl_xor_sync(0xffffffffu, s, 2);
    q += __shfl_xor_sync(0xffffffffu, q, 2);
    float mean = s * (1.f / 16.f);
    float var  = q * (1.f / 16.f) - mean * mean;
    float rstd = rsqrtf(var + 1e-5f);
    int c = 4 * l;
    float4 w4 = *(const float4*)&gnw[c];
    float4 b4 = *(const float4*)&gnb[c];
    float4 g4 = *(const float4*)&g_scratch[OFF_STYLE + c];
    float4 e4 = *(const float4*)&g_scratch[OFF_STYLE + 128 + c];
    float h0 = ((v.x - mean) * rstd * w4.x + b4.x) * (1.f + g4.x) + e4.x;
    float h1 = ((v.y - mean) * rstd * w4.y + b4.y) * (1.f + g4.y) + e4.y;
    float h2 = ((v.z - mean) * rstd * w4.z + b4.z) * (1.f + g4.z) + e4.z;
    float h3 = ((v.w - mean) * rstd * w4.w + b4.w) * (1.f + g4.w) + e4.w;
    uint32_t l0, l1;
    uint32_t p0 = pack_split(h0, h1, l0);
    uint32_t p1 = pack_split(h2, h3, l1);
    uint32_t* st = (uint32_t*)(g_scratch + OFF_HMOD);
    st[(size_t)n * 64 + 2 * l]     = p0;
    st[(size_t)n * 64 + 2 * l + 1] = p1;
    st[(size_t)NN * 64 + (size_t)n * 64 + 2 * l]     = l0;
    st[(size_t)NN * 64 + (size_t)n * 64 + 2 * l + 1] = l1;
}

// ======================================================================
// HMMA bf16 3-term split GEMM core
// ======================================================================
constexpr int SLDA  = 136;
constexpr int TILEH = 128 * SLDA;
constexpr int AHI_H = 0;
constexpr int ALO_H = TILEH;
constexpr int BHI_H = 2 * TILEH;
constexpr int BLO_H = 3 * TILEH;
constexpr int SMEM_BYTES = 4 * TILEH * 2;

__device__ __forceinline__ void ld_tile(char* dsm, int half_base, const uint32_t* __restrict__ src,
                                        int ld32, int k32off, int rowBase, int rowMax, int tid) {
#pragma unroll
    for (int it = 0; it < 8; it++) {
        int idx = it * 256 + tid;
        int row = idx >> 4, c16 = idx & 15;
        int gr = rowBase + row;
        if (gr > rowMax) gr = rowMax;
        uint4 v = *(const uint4*)(src + (size_t)gr * ld32 + k32off + c16 * 4);
        *(uint4*)(dsm + 2 * (half_base + row * SLDA) + c16 * 16) = v;
    }
}

__device__ __forceinline__ void mma_chunk(uint32_t sb, int wm, int wn, int lane, float c[4][4][4]) {
    const int lrA = lane & 15, lcA = (lane >> 4) << 3;
    const int lrB = lane & 7,  lcB = ((lane >> 3) & 1) << 3;
#pragma unroll
    for (int ks = 0; ks < 8; ks++) {
        uint32_t ah[4][4], al[4][4];
#pragma unroll
        for (int mi = 0; mi < 4; mi++) {
            uint32_t addr = sb + 2u * (uint32_t)((wm * 64 + mi * 16 + lrA) * SLDA + ks * 16 + lcA);
            ldsm_x4(ah[mi][0], ah[mi][1], ah[mi][2], ah[mi][3], addr);
            ldsm_x4(al[mi][0], al[mi][1], al[mi][2], al[mi][3], addr + 2u * (uint32_t)ALO_H);
        }
#pragma unroll
        for (int ni = 0; ni < 4; ni++) {
            uint32_t baddr = sb + 2u * (uint32_t)(BHI_H + (wn * 32 + ni * 8 + lrB) * SLDA + ks * 16 + lcB);
            uint32_t bh0, bh1, bl0, bl1;
            ldsm_x2(bh0, bh1, baddr);
            ldsm_x2(bl0, bl1, baddr + 2u * (uint32_t)(BLO_H - BHI_H));
#pragma unroll
            for (int mi = 0; mi < 4; mi++) {
                mma_bf16(c[mi][ni], ah[mi][0], ah[mi][1], ah[mi][2], ah[mi][3], bh0, bh1);
                mma_bf16(c[mi][ni], al[mi][0], al[mi][1], al[mi][2], al[mi][3], bh0, bh1);
                mma_bf16(c[mi][ni], ah[mi][0], ah[mi][1], ah[mi][2], ah[mi][3], bl0, bl1);
            }
        }
    }
}

// generic GEMM: modes 0 plain fp32, 1 GELU->packed bf16, 2 fp32 + extra residual
__global__ void __launch_bounds__(256, 1) k_mma(
    const uint32_t* __restrict__ Ahi, const uint32_t* __restrict__ Alo, int lda32,
    const uint32_t* __restrict__ Bhi, const uint32_t* __restrict__ Blo, int ldb32,
    const float* __restrict__ bias, int mode,
    float* __restrict__ Cf, int ldc, const float* __restrict__ extra,
    uint32_t* __restrict__ Cohi, uint32_t* __restrict__ Colo, int ldco,
    int M, int K)
{
    extern __shared__ __align__(16) char dsm[];
    const int tid = threadIdx.x;
    const int w = tid >> 5, lane = tid & 31;
    const uint32_t sb = s2u(dsm);
    const int rowBase = blockIdx.x * 128;
    const int nBase = blockIdx.y * 128;
    const int wm = w & 1, wn = w >> 1;

    const uint32_t* bh = Bhi + (size_t)nBase * ldb32;
    const uint32_t* bl = Blo + (size_t)nBase * ldb32;

    float c[4][4][4];
#pragma unroll
    for (int i = 0; i < 4; i++)
#pragma unroll
        for (int j = 0; j < 4; j++)
#pragma unroll
            for (int q = 0; q < 4; q++) c[i][j][q] = 0.f;

    for (int kt = 0; kt < K; kt += 128) {
        int k32 = kt >> 1;
        ld_tile(dsm, AHI_H, Ahi, lda32, k32, rowBase, M - 1, tid);
        ld_tile(dsm, ALO_H, Alo, lda32, k32, rowBase, M - 1, tid);
        ld_tile(dsm, BHI_H, bh, ldb32, k32, 0, 127, tid);
        ld_tile(dsm, BLO_H, bl, ldb32, k32, 0, 127, tid);
        __syncthreads();
        mma_chunk(sb, wm, wn, lane, c);
        __syncthreads();
    }

    const int gq = lane >> 2;
    const int c2 = (lane & 3) * 2;
#pragma unroll
    for (int mi = 0; mi < 4; mi++) {
#pragma unroll
        for (int ni = 0; ni < 4; ni++) {
            int colg = nBase + wn * 32 + ni * 8 + c2;
            float2 bb = *(const float2*)&bias[colg];
#pragma unroll
            for (int half = 0; half < 2; half++) {
                int gr = rowBase + wm * 64 + mi * 16 + gq + half * 8;
                if (gr >= M) continue;
                float v0 = c[mi][ni][half * 2 + 0] + bb.x;
                float v1 = c[mi][ni][half * 2 + 1] + bb.y;
                if (mode == 0) {
                    *(float2*)&Cf[(size_t)gr * ldc + colg] = make_float2(v0, v1);
                } else if (mode == 1) {
                    uint32_t l, h = pack_split(geluf(v0), geluf(v1), l);
                    Cohi[(size_t)gr * ldco + (colg >> 1)] = h;
                    Colo[(size_t)gr * ldco + (colg >> 1)] = l;
                } else {
                    float2 r4 = *(const float2*)&extra[(size_t)gr * 128 + colg];
                    *(float2*)&Cf[(size_t)gr * ldc + colg] = make_float2(v0 + r4.x, v1 + r4.y);
                }
            }
        }
    }
}

// fused node-transform GEMM: A (HM bf16) loaded once, loop over Wl/Wr/We
// t0: x_l -> P fp32 + XLH fp16 ; t1: x_r -> XR fp32 ; t2: A=xl+acc -> AH fp16, B=xr-acc -> P+256 fp32
__global__ void __launch_bounds__(256, 1) k_mma3(
    const uint32_t* __restrict__ Ahi, const uint32_t* __restrict__ Alo,
    const float* __restrict__ bl_, const float* __restrict__ br_,
    float* __restrict__ P, float* __restrict__ XR,
    __half* __restrict__ XLH, __half* __restrict__ AH, int M)
{
    extern __shared__ __align__(16) char dsm[];
    const int tid = threadIdx.x;
    const int w = tid >> 5, lane = tid & 31;
    const uint32_t sb = s2u(dsm);
    const int rowBase = blockIdx.x * 128;
    const int wm = w & 1, wn = w >> 1;
    const uint32_t* ws = (const uint32_t*)(g_scratch + OFF_WSTG);
    const int wsoff[3] = {WS_WL, WS_WR, WS_WE};

    ld_tile(dsm, AHI_H, Ahi, 64, 0, rowBase, M - 1, tid);
    ld_tile(dsm, ALO_H, Alo, 64, 0, rowBase, M - 1, tid);
    ld_tile(dsm, BHI_H, ws + wsoff[0], 64, 0, 0, 127, tid);
    ld_tile(dsm, BLO_H, ws + wsoff[0] + 8192, 64, 0, 0, 127, tid);
    __syncthreads();

    const int gq = lane >> 2;
    const int c2 = (lane & 3) * 2;

#pragma unroll
    for (int t = 0; t < 3; t++) {
        float c[4][4][4];
#pragma unroll
        for (int i = 0; i < 4; i++)
#pragma unroll
            for (int j = 0; j < 4; j++)
#pragma unroll
                for (int q = 0; q < 4; q++) c[i][j][q] = 0.f;

        mma_chunk(sb, wm, wn, lane, c);

#pragma unroll
        for (int mi = 0; mi < 4; mi++) {
#pragma unroll
            for (int ni = 0; ni < 4; ni++) {
                int colg = wn * 32 + ni * 8 + c2;
                float2 bb = make_float2(0.f, 0.f);
                if (t == 0) bb = *(const float2*)&bl_[colg];
                else if (t == 1) bb = *(const float2*)&br_[colg];
#pragma unroll
                for (int half = 0; half < 2; half++) {
                    int gr = rowBase + wm * 64 + mi * 16 + gq + half * 8;
                    if (gr >= M) continue;
                    float v0 = c[mi][ni][half * 2 + 0] + bb.x;
                    float v1 = c[mi][ni][half * 2 + 1] + bb.y;
                    if (t == 0) {
                        *(float2*)&P[(size_t)gr * 384 + colg] = make_float2(v0, v1);
                        *(__half2*)&XLH[(size_t)gr * 128 + colg] = __floats2half2_rn(v0, v1);
                    } else if (t == 1) {
                        *(float2*)&XR[(size_t)gr * 128 + colg] = make_float2(v0, v1);
                    } else {
                        float2 xl = *(const float2*)&P[(size_t)gr * 384 + colg];
                        float2 xr = *(const float2*)&XR[(size_t)gr * 128 + colg];
                        *(__half2*)&AH[(size_t)gr * 128 + colg] = __floats2half2_rn(xl.x + v0, xl.y + v1);
                        *(float2*)&P[(size_t)gr * 384 + 256 + colg] = make_float2(xr.x - v0, xr.y - v1);
                    }
                }
            }
        }
        __syncthreads();
        if (t < 2) {
            ld_tile(dsm, BHI_H, ws + wsoff[t + 1], 64, 0, 0, 127, tid);
            ld_tile(dsm, BLO_H, ws + wsoff[t + 1] + 8192, 64, 0, 0, 127, tid);
            __syncthreads();
        }
    }
}

// ---------------- fused GAT attention: online softmax, fp16 gathers, unroll x2 ----------------
__global__ void __launch_bounds__(256) k_attn(const float* __restrict__ pos,
                                              const float* __restrict__ We,
                                              const float* __restrict__ att,
                                              const __half* __restrict__ XLH,
                                              const __half* __restrict__ AH, int E, int M) {
    int n = blockIdx.x * 8 + (threadIdx.x >> 5);
    if (n >= M) return;
    int l = threadIdx.x & 31;
    const int* list = csr_base();
    const int* off = list + E;
    int off0 = off[n], off1 = off[n + 1];

    float2 pd = ((const float2*)pos)[n];
    float4 b4 = *(const float4*)(g_scratch + OFF_P + (size_t)n * 384 + 256 + 4 * l);
    float4 at = *(const float4*)(att + 4 * l);
    float4 c0 = *(const float4*)(We + 128 * 128 + 4 * l);
    float4 c1 = *(const float4*)(We + 129 * 128 + 4 * l);

    float mh = -1e30f, den = 0.f;
    float4 acc = make_float4(0.f, 0.f, 0.f, 0.f);

    int p = off0;
    for (; p + 1 < off1; p += 2) {
        int s0 = list[p];
        int s1 = list[p + 1];
        float2 ps0 = ((const float2*)pos)[s0];
        float2 ps1 = ((const float2*)pos)[s1];
        uint2 au0 = ((const uint2*)(AH + (size_t)s0 * 128))[l];
        uint2 xu0 = ((const uint2*)(XLH + (size_t)s0 * 128))[l];
        uint2 au1 = ((const uint2*)(AH + (size_t)s1 * 128))[l];
        uint2 xu1 = ((const uint2*)(XLH + (size_t)s1 * 128))[l];
        float2 a0lo = __half22float2(*(__half2*)&au0.x);
        float2 a0hi = __half22float2(*(__half2*)&au0.y);
        float2 x0lo = __half22float2(*(__half2*)&xu0.x);
        float2 x0hi = __half22float2(*(__half2*)&xu0.y);
        float2 a1lo = __half22float2(*(__half2*)&au1.x);
        float2 a1hi = __half22float2(*(__half2*)&au1.y);
        float2 x1lo = __half22float2(*(__half2*)&xu1.x);
        float2 x1hi = __half22float2(*(__half2*)&xu1.y);

        float rx0 = ps0.x - pd.x, ry0 = ps0.y - pd.y;
        float d0 = rx0 * rx0 + ry0 * ry0 + 1e-8f;
        float ox0 = -ry0 / d0, oy0 = rx0 / d0;
        float rx1 = ps1.x - pd.x, ry1 = ps1.y - pd.y;
        float d1 = rx1 * rx1 + ry1 * ry1 + 1e-8f;
        float ox1 = -ry1 / d1, oy1 = rx1 / d1;

        float t0x = a0lo.x + b4.x + ox0 * c0.x + oy0 * c1.x;
        float t0y = a0lo.y + b4.y + ox0 * c0.y + oy0 * c1.y;
        float t0z = a0hi.x + b4.z + ox0 * c0.z + oy0 * c1.z;
        float t0w = a0hi.y + b4.w + ox0 * c0.w + oy0 * c1.w;
        float t1x = a1lo.x + b4.x + ox1 * c0.x + oy1 * c1.x;
        float t1y = a1lo.y + b4.y + ox1 * c0.y + oy1 * c1.y;
        float t1z = a1hi.x + b4.z + ox1 * c0.z + oy1 * c1.z;
        float t1w = a1hi.y + b4.w + ox1 * c0.w + oy1 * c1.w;
        t0x = t0x > 0.f ? t0x : 0.2f * t0x;
        t0y = t0y > 0.f ? t0y : 0.2f * t0y;
        t0z = t0z > 0.f ? t0z : 0.2f * t0z;
        t0w = t0w > 0.f ? t0w : 0.2f * t0w;
        t1x = t1x > 0.f ? t1x : 0.2f * t1x;
        t1y = t1y > 0.f ? t1y : 0.2f * t1y;
        t1z = t1z > 0.f ? t1z : 0.2f * t1z;
        t1w = t1w > 0.f ? t1w : 0.2f * t1w;
        float lg0 = t0x * at.x + t0y * at.y + t0z * at.z + t0w * at.w;
        float lg1 = t1x * at.x + t1y * at.y + t1z * at.z + t1w * at.w;
        lg0 += __shfl_xor_sync(0xffffffffu, lg0, 4);
        lg1 += __shfl_xor_sync(0xffffffffu, lg1, 4);
        lg0 += __shfl_xor_sync(0xffffffffu, lg0, 2);
        lg1 += __shfl_xor_sync(0xffffffffu, lg1, 2);
        lg0 += __shfl_xor_sync(0xffffffffu, lg0, 1);
        lg1 += __shfl_xor_sync(0xffffffffu, lg1, 1);

        float mnew = fmaxf(mh, fmaxf(lg0, lg1));
        float scale = __expf(mh - mnew);
        float al0 = __expf(lg0 - mnew);
        float al1 = __expf(lg1 - mnew);
        den = den * scale + al0 + al1;
        acc.x = acc.x * scale + x0lo.x * al0 + x1lo.x * al1;
        acc.y = acc.y * scale + x0lo.y * al0 + x1lo.y * al1;
        acc.z = acc.z * scale + x0hi.x * al0 + x1hi.x * al1;
        acc.w = acc.w * scale + x0hi.y * al0 + x1hi.y * al1;
        mh = mnew;
    }
    if (p < off1) {
        int s = list[p];
        float2 ps = ((const float2*)pos)[s];
        uint2 au = ((const uint2*)(AH + (size_t)s * 128))[l];
        uint2 xu = ((const uint2*)(XLH + (size_t)s * 128))[l];
        float2 alo = __half22float2(*(__half2*)&au.x);
        float2 ahi = __half22float2(*(__half2*)&au.y);
        float2 xlo = __half22float2(*(__half2*)&xu.x);
        float2 xhi = __half22float2(*(__half2*)&xu.y);
        float rx = ps.x - pd.x, ry = ps.y - pd.y;
        float dsq = rx * rx + ry * ry + 1e-8f;
        float ox = -ry / dsq, oy = rx / dsq;
        float xx = alo.x + b4.x + ox * c0.x + oy * c1.x;
        float xy = alo.y + b4.y + ox * c0.y + oy * c1.y;
        float xz = ahi.x + b4.z + ox * c0.z + oy * c1.z;
        float xw = ahi.y + b4.w + ox * c0.w + oy * c1.w;
        xx = xx > 0.f ? xx : 0.2f * xx;
        xy = xy > 0.f ? xy : 0.2f * xy;
        xz = xz > 0.f ? xz : 0.2f * xz;
        xw = xw > 0.f ? xw : 0.2f * xw;
        float lg = xx * at.x + xy * at.y + xz * at.z + xw * at.w;
        lg += __shfl_xor_sync(0xffffffffu, lg, 4);
        lg += __shfl_xor_sync(0xffffffffu, lg, 2);
        lg += __shfl_xor_sync(0xffffffffu, lg, 1);
        float mnew = fmaxf(mh, lg);
        float scale = __expf(mh - mnew);
        float al = __expf(lg - mnew);
        den = den * scale + al;
        acc.x = acc.x * scale + xlo.x * al;
        acc.y = acc.y * scale + xlo.y * al;
        acc.z = acc.z * scale + xhi.x * al;
        acc.w = acc.w * scale + xhi.y * al;
        mh = mnew;
    }

    float r = 1.f / (den + 1e-16f);
    acc.x *= r; acc.y *= r; acc.z *= r; acc.w *= r;

    uint32_t l0, l1;
    uint32_t h0 = pack_split(acc.x, acc.y, l0);
    uint32_t h1 = pack_split(acc.z, acc.w, l1);
    uint32_t* st = (uint32_t*)(g_scratch + OFF_HMOD);
    st[(size_t)n * 64 + 2 * l]     = h0;
    st[(size_t)n * 64 + 2 * l + 1] = h1;
    st[(size_t)NN * 64 + (size_t)n * 64 + 2 * l]     = l0;
    st[(size_t)NN * 64 + (size_t)n * 64 + 2 * l + 1] = l1;
}

// ---------------- LayerNorm -> packed bf16 hi/lo staging ----------------
__global__ void __launch_bounds__(256) k_ln(const float* __restrict__ lnw,
                                            const float* __restrict__ lnb, int M) {
    int n = blockIdx.x * 8 + (threadIdx.x >> 5);
    if (n >= M) return;
    int l = threadIdx.x & 31;
    float4 v = ((const float4*)(g_scratch + OFF_AGGR2 + (size_t)n * 128))[l];
    float s = v.x + v.y + v.z + v.w;
    float q = v.x * v.x + v.y * v.y + v.z * v.z + v.w * v.w;
#pragma unroll
    for (int o = 16; o; o >>= 1) {
        s += __shfl_xor_sync(0xffffffffu, s, o);
        q += __shfl_xor_sync(0xffffffffu, q, o);
    }
    float mean = s * (1.f / 128.f);
    float var  = q * (1.f / 128.f) - mean * mean;
    float rstd = rsqrtf(var + 1e-5f);
    float4 w = ((const float4*)lnw)[l];
    float4 b = ((const float4*)lnb)[l];
    float4 o4;
    o4.x = (v.x - mean) * rstd * w.x + b.x;
    o4.y = (v.y - mean) * rstd * w.y + b.y;
    o4.z = (v.z - mean) * rstd * w.z + b.z;
    o4.w = (v.w - mean) * rstd * w.w + b.w;
    uint32_t l0, l1;
    uint32_t h0 = pack_split(o4.x, o4.y, l0);
    uint32_t h1 = pack_split(o4.z, o4.w, l1);
    uint32_t* st = (uint32_t*)(g_scratch + OFF_HMOD);
    st[(size_t)n * 64 + 2 * l]     = h0;
    st[(size_t)n * 64 + 2 * l + 1] = h1;
    st[(size_t)NN * 64 + (size_t)n * 64 + 2 * l]     = l0;
    st[(size_t)NN * 64 + (size_t)n * 64 + 2 * l + 1] = l1;
}

// ---------------- launch ----------------
extern "C" void kernel_launch(void* const* d_in, const int* in_sizes, int n_in,
                              void* d_out, int out_size) {
    const float* h_target = (const float*)d_in[0];
    const float* h_source = (const float*)d_in[1];
    const int* ei      = (const int*)d_in[2];
    const float* pos   = (const float*)d_in[3];
    const float* t_emb = (const float*)d_in[4];
    const float* gn_w  = (const float*)d_in[5];
    const float* gn_b  = (const float*)d_in[6];
    const float* fcW   = (const float*)d_in[7];
    const float* fcb   = (const float*)d_in[8];
    const float* Wl    = (const float*)d_in[9];
    const float* bl    = (const float*)d_in[10];
    const float* Wr    = (const float*)d_in[11];
    const float* br    = (const float*)d_in[12];
    const float* We    = (const float*)d_in[13];
    const float* att   = (const float*)d_in[14];
    const float* gatb  = (const float*)d_in[15];
    const float* Wp    = (const float*)d_in[16];
    const float* bp    = (const float*)d_in[17];
    const float* lnw   = (const float*)d_in[18];
    const float* lnb   = (const float*)d_in[19];
    const float* W1    = (const float*)d_in[20];
    const float* b1    = (const float*)d_in[21];
    const float* W2    = (const float*)d_in[22];
    const float* b2    = (const float*)d_in[23];

    int M = in_sizes[0] / 128; if (M > NN) M = NN;
    int E = in_sizes[2] / 2;   if (E > EE) E = EE;

    float* sc = nullptr;
    cudaGetSymbolAddress((void**)&sc, g_scratch);
    float* P     = sc + OFF_P;
    float* AGGR2 = sc + OFF_AGGR2;
    float* BIAS2 = sc + OFF_BIAS2;
    uint32_t* HMB  = (uint32_t*)(sc + OFF_HMOD);
    __half* XLH  = (__half*)(sc + OFF_LOGIT);
    __half* AH   = (__half*)(sc + OFF_AH);
    uint32_t* Z1HI = (uint32_t*)(sc + OFF_P) + (size_t)NN * 128;
    uint32_t* Z1LO = Z1HI + (size_t)NN * 128;
    uint32_t* WS   = (uint32_t*)(sc + OFF_WSTG);

    cudaFuncSetAttribute(k_mma,  cudaFuncAttributeMaxDynamicSharedMemorySize, SMEM_BYTES);
    cudaFuncSetAttribute(k_mma3, cudaFuncAttributeMaxDynamicSharedMemorySize, SMEM_BYTES);

    dim3 blk(256);
    dim3 g1((M + 127) / 128, 1);
    dim3 g2((M + 127) / 128, 2);

    int ZB = (M + 255) / 256;
    int setupBlocks = 2 + ZB + 32 * 4 + 64 * 2;
    k_setup<<<setupBlocks, 256>>>(ei, t_emb, fcW, fcb, gatb, Wp, bp,
                                  Wl, Wr, We, W1, W2, E, M);
    k_prep<<<(E + 255) / 256, 256>>>(ei, E, M);
    k_scan<<<1, 1024>>>(E, M);
    k_fill<<<(E + 255) / 256, 256>>>(ei, E, M);

    k_adagn<<<(M + 7) / 8, 256>>>(h_source, gn_w, gn_b, M);

    // node transforms: x_l->P+XLH, x_r->AGGR2(temp), A->AH fp16 / B->P+256 fp32
    k_mma3<<<g1, blk, SMEM_BYTES>>>(HMB, HMB + (size_t)NN * 64, bl, br, P, AGGR2, XLH, AH, M);

    // fused GAT: online softmax, fp16 gathers -> HMOD (bf16 hi/lo)
    k_attn<<<(M + 7) / 8, 256>>>(pos, We, att, XLH, AH, E, M);

    // post_gat: aggr(bf16)@Wp + bias2 -> AGGR2 fp32
    k_mma<<<g1, blk, SMEM_BYTES>>>(HMB, HMB + (size_t)NN * 64, 64,
                                   WS + WS_WP, WS + WS_WP + 8192, 64,
                                   BIAS2, 0, AGGR2, 128, nullptr, nullptr, nullptr, 0, M, 128);
    k_ln<<<(M + 7) / 8, 256>>>(lnw, lnb, M);
    // W1 + GELU -> z1 bf16
    k_mma<<<g2, blk, SMEM_BYTES>>>(HMB, HMB + (size_t)NN * 64, 64,
                                   WS + WS_W1, WS + WS_W1 + 16384, 64,
                                   b1, 1, nullptr, 0, nullptr, Z1HI, Z1LO, 128, M, 128);
    // W2 + residual -> d_out
    k_mma<<<g1, blk, SMEM_BYTES>>>(Z1HI, Z1LO, 128,
                                   WS + WS_W2, WS + WS_W2 + 16384, 128,
                                   b2, 2, (float*)d_out, 128, h_target, nullptr, nullptr, 0, M, 256);
}